// round 1
// baseline (speedup 1.0000x reference)
#include <cuda_runtime.h>

// Problem constants
#define BB   128
#define CIN  2
#define HIDC 150
#define AA   8
#define KIT  30
#define G    49
#define HP   51
#define GG   (G*G)      // 2401
#define HPHP (HP*HP)    // 2601

// ---------------- scratch (device globals; no allocations allowed) ----------
__device__ float g_h  [BB*HIDC*GG];     // conv1 out
__device__ float g_h2 [BB*HIDC*GG];     // conv2 out
__device__ float g_tr [BB*AA*9*HPHP];   // trans -> softmaxed in place (sT)
__device__ float g_rew[BB*HPHP];        // reward
__device__ float g_vbuf[2][BB*HPHP];    // VI ping-pong
__device__ float g_q  [BB*AA*HPHP];     // last-iteration q
__device__ float g_wT2 [HIDC*9*HIDC];   // conv2 weights [ci][k][co]
__device__ float g_wTrt[HIDC*9*76];     // reward+trans weights [ci][k][cc], cc0=reward, 1..72=trans, pad 76

// ---------------- weight transpose prep -------------------------------------
__global__ void prep_k(const float* __restrict__ h2w,
                       const float* __restrict__ rw,
                       const float* __restrict__ tw) {
    int i = blockIdx.x * blockDim.x + threadIdx.x;
    if (i < HIDC*9*HIDC) {
        int co = i % HIDC;
        int k  = (i / HIDC) % 9;
        int ci = i / (9*HIDC);
        g_wT2[i] = h2w[(co*HIDC + ci)*9 + k];
    }
    int j = i - HIDC*9*HIDC;
    if (j >= 0 && j < HIDC*9*76) {
        int cc = j % 76;
        int k  = (j / 76) % 9;
        int ci = j / (9*76);
        float v = 0.f;
        if (cc == 0)       v = rw[ci*9 + k];
        else if (cc <= 72) v = tw[((cc-1)*HIDC + ci)*9 + k];
        g_wTrt[j] = v;
    }
}

// ---------------- conv1: grid[B,2,49,49] -> h[B,150,49,49], relu, pad=1 ------
__global__ void conv1_k(const float* __restrict__ gin,
                        const float* __restrict__ w,
                        const float* __restrict__ bias) {
    __shared__ float ws[HIDC*CIN*9];
    __shared__ float bs[HIDC];
    int t = threadIdx.x;
    for (int i = t; i < HIDC*CIN*9; i += blockDim.x) ws[i] = w[i];
    for (int i = t; i < HIDC; i += blockDim.x) bs[i] = bias[i];
    __syncthreads();
    int tid = blockIdx.x * blockDim.x + t;
    if (tid >= BB*GG) return;
    int b = tid / GG, pos = tid % GG, y = pos / G, x = pos % G;
    float gv[CIN][9];
    #pragma unroll
    for (int ci = 0; ci < CIN; ci++)
        #pragma unroll
        for (int k = 0; k < 9; k++) {
            int r = y + k/3 - 1, c = x + k%3 - 1;
            gv[ci][k] = (r >= 0 && r < G && c >= 0 && c < G)
                        ? gin[(b*CIN + ci)*GG + r*G + c] : 0.f;
        }
    for (int co = 0; co < HIDC; co++) {
        float acc = bs[co];
        #pragma unroll
        for (int ci = 0; ci < CIN; ci++)
            #pragma unroll
            for (int k = 0; k < 9; k++)
                acc += gv[ci][k] * ws[(co*CIN + ci)*9 + k];
        g_h[(b*HIDC + co)*GG + pos] = fmaxf(acc, 0.f);
    }
}

// ---------------- conv2: h -> h2, 150->150, 3x3 pad=1, relu ------------------
// CTA = (y, b). 224 threads; active 210: cg=t/7 (30 groups of 5 co), xg=t%7 (7 groups of 7 x).
#define C2CI 6
__global__ void conv2_k(const float* __restrict__ bias) {
    __shared__ float inS[C2CI][3][52];
    __shared__ float wS[C2CI*9*HIDC];
    int y = blockIdx.x, b = blockIdx.y;
    int t = threadIdx.x;
    int cg = t / 7, xg = t % 7;
    int co0 = cg * 5, x0 = xg * 7;
    float acc[5][7];
    #pragma unroll
    for (int j = 0; j < 5; j++)
        #pragma unroll
        for (int i = 0; i < 7; i++) acc[j][i] = 0.f;

    for (int ci0 = 0; ci0 < HIDC; ci0 += C2CI) {
        for (int i = t; i < C2CI*9*HIDC; i += 224)
            wS[i] = g_wT2[ci0*9*HIDC + i];
        for (int idx = t; idx < C2CI*3*52; idx += 224) {
            int c  = idx / (3*52);
            int rr = (idx / 52) % 3;
            int ii = idx % 52;
            int row = y + rr - 1, col = ii - 1;
            float v = 0.f;
            if (row >= 0 && row < G && col >= 0 && col < G)
                v = g_h[((b*HIDC + ci0 + c)*G + row)*G + col];
            inS[c][rr][ii] = v;
        }
        __syncthreads();
        if (cg < 30) {
            #pragma unroll
            for (int c = 0; c < C2CI; c++) {
                #pragma unroll
                for (int k = 0; k < 9; k++) {
                    int dy = k / 3, dx = k % 3;
                    float w0 = wS[(c*9 + k)*HIDC + co0 + 0];
                    float w1 = wS[(c*9 + k)*HIDC + co0 + 1];
                    float w2 = wS[(c*9 + k)*HIDC + co0 + 2];
                    float w3 = wS[(c*9 + k)*HIDC + co0 + 3];
                    float w4 = wS[(c*9 + k)*HIDC + co0 + 4];
                    const float* ip = &inS[c][dy][x0 + dx];
                    #pragma unroll
                    for (int i = 0; i < 7; i++) {
                        float iv = ip[i];
                        acc[0][i] += w0 * iv;
                        acc[1][i] += w1 * iv;
                        acc[2][i] += w2 * iv;
                        acc[3][i] += w3 * iv;
                        acc[4][i] += w4 * iv;
                    }
                }
            }
        }
        __syncthreads();
    }
    if (cg < 30) {
        #pragma unroll
        for (int j = 0; j < 5; j++) {
            float bv = bias[co0 + j];
            #pragma unroll
            for (int i = 0; i < 7; i++)
                g_h2[((b*HIDC + co0 + j)*G + y)*G + x0 + i] = fmaxf(acc[j][i] + bv, 0.f);
        }
    }
}

// ------------- reward+trans conv: h2 -> [B,73,51,51], 3x3 pad=2, no bias -----
// CTA = (y51, b). 128 threads; active 120: cg=t/8 (15 groups of 5 cc), xg=t%8 (8 groups of 7 x).
#define RTCI 10
#define RTW  76
__global__ void convrt_k() {
    __shared__ float inS[RTCI][3][60];
    __shared__ float wS[RTCI*9*RTW];
    int y = blockIdx.x, b = blockIdx.y;   // y < 51
    int t = threadIdx.x;
    int cg = t / 8, xg = t % 8;
    int co0 = cg * 5, x0 = xg * 7;
    float acc[5][7];
    #pragma unroll
    for (int j = 0; j < 5; j++)
        #pragma unroll
        for (int i = 0; i < 7; i++) acc[j][i] = 0.f;

    for (int ci0 = 0; ci0 < HIDC; ci0 += RTCI) {
        for (int i = t; i < RTCI*9*RTW; i += 128)
            wS[i] = g_wTrt[ci0*9*RTW + i];
        for (int idx = t; idx < RTCI*3*60; idx += 128) {
            int c  = idx / (3*60);
            int rr = (idx / 60) % 3;
            int ii = idx % 60;
            int row = y + rr - 2, col = ii - 2;
            float v = 0.f;
            if (row >= 0 && row < G && col >= 0 && col < G && ii < 53)
                v = g_h2[((b*HIDC + ci0 + c)*G + row)*G + col];
            inS[c][rr][ii] = v;
        }
        __syncthreads();
        if (t < 120) {
            #pragma unroll
            for (int c = 0; c < RTCI; c++) {
                #pragma unroll
                for (int k = 0; k < 9; k++) {
                    int dy = k / 3, dx = k % 3;
                    float w0 = wS[(c*9 + k)*RTW + co0 + 0];
                    float w1 = wS[(c*9 + k)*RTW + co0 + 1];
                    float w2 = wS[(c*9 + k)*RTW + co0 + 2];
                    float w3 = wS[(c*9 + k)*RTW + co0 + 3];
                    float w4 = wS[(c*9 + k)*RTW + co0 + 4];
                    const float* ip = &inS[c][dy][x0 + dx];
                    #pragma unroll
                    for (int i = 0; i < 7; i++) {
                        float iv = ip[i];
                        acc[0][i] += w0 * iv;
                        acc[1][i] += w1 * iv;
                        acc[2][i] += w2 * iv;
                        acc[3][i] += w3 * iv;
                        acc[4][i] += w4 * iv;
                    }
                }
            }
        }
        __syncthreads();
    }
    if (t < 120) {
        #pragma unroll
        for (int j = 0; j < 5; j++) {
            int cc = co0 + j;
            if (cc >= 73) continue;
            #pragma unroll
            for (int i = 0; i < 7; i++) {
                int x = x0 + i;
                if (x >= HP) continue;
                if (cc == 0) g_rew[b*HPHP + y*HP + x] = acc[j][i];
                else         g_tr[(b*72 + (cc-1))*HPHP + y*HP + x] = acc[j][i];
            }
        }
    }
}

// ---------------- softmax over the 9 taps (in place on g_tr) ----------------
__global__ void softmax_k() {
    int tid = blockIdx.x * blockDim.x + threadIdx.x;
    if (tid >= BB*AA*HPHP) return;
    int pos = tid % HPHP;
    int ba  = tid / HPHP;              // b*8 + a
    int base = ba*9*HPHP + pos;        // b*72 + a*9 == 9*(b*8+a)
    float v[9];
    float m = -1e30f;
    #pragma unroll
    for (int k = 0; k < 9; k++) { v[k] = g_tr[base + k*HPHP]; m = fmaxf(m, v[k]); }
    float s = 0.f;
    #pragma unroll
    for (int k = 0; k < 9; k++) { v[k] = expf(v[k] - m); s += v[k]; }
    float inv = 1.f / s;
    #pragma unroll
    for (int k = 0; k < 9; k++) g_tr[base + k*HPHP] = v[k] * inv;
}

// ---------------- one value-iteration step ----------------------------------
__global__ void vi_step_k(int iter, int store_q) {
    int tid = blockIdx.x * blockDim.x + threadIdx.x;
    if (tid >= BB*HPHP) return;
    int b = tid / HPHP, pos = tid % HPHP, y = pos / HP, x = pos % HP;
    const float* vin = g_vbuf[(iter & 1) ^ 1];
    float p[9];
    if (iter == 0) {
        #pragma unroll
        for (int k = 0; k < 9; k++) p[k] = 0.f;
    } else {
        #pragma unroll
        for (int k = 0; k < 9; k++) {
            int r = y + k/3 - 1, c = x + k%3 - 1;
            p[k] = (r >= 0 && r < HP && c >= 0 && c < HP)
                   ? vin[b*HPHP + r*HP + c] : 0.f;
        }
    }
    float r0 = g_rew[tid];
    float vmax = -1e30f;
    #pragma unroll
    for (int a = 0; a < AA; a++) {
        int base = (b*72 + a*9)*HPHP + pos;
        float q = r0;
        #pragma unroll
        for (int k = 0; k < 9; k++) q += g_tr[base + k*HPHP] * p[k];
        if (store_q) g_q[(b*AA + a)*HPHP + pos] = q;
        vmax = fmaxf(vmax, q);
    }
    g_vbuf[iter & 1][tid] = vmax;
}

// ---------------- head: q[:, :, :49, :49] -> 150 -> 8 -----------------------
__global__ void head_k(const float* __restrict__ a1w, const float* __restrict__ a1b,
                       const float* __restrict__ a2w, const float* __restrict__ a2b,
                       float* __restrict__ out) {
    __shared__ float a1s[HIDC*AA];
    __shared__ float a2s[AA*HIDC];
    __shared__ float b1s[HIDC];
    __shared__ float b2s[AA];
    int t = threadIdx.x;
    for (int i = t; i < HIDC*AA; i += blockDim.x) { a1s[i] = a1w[i]; a2s[i] = a2w[i]; }
    for (int i = t; i < HIDC; i += blockDim.x) b1s[i] = a1b[i];
    if (t < AA) b2s[t] = a2b[t];
    __syncthreads();
    int tid = blockIdx.x * blockDim.x + t;
    if (tid >= BB*GG) return;
    int b = tid / GG, pos = tid % GG, y = pos / G, x = pos % G;
    float qv[AA];
    #pragma unroll
    for (int a = 0; a < AA; a++) qv[a] = g_q[(b*AA + a)*HPHP + y*HP + x];
    float lg[AA];
    #pragma unroll
    for (int a = 0; a < AA; a++) lg[a] = 0.f;
    for (int c = 0; c < HIDC; c++) {
        float m = b1s[c];
        #pragma unroll
        for (int a = 0; a < AA; a++) m += qv[a] * a1s[c*AA + a];
        m = fmaxf(m, 0.f);
        #pragma unroll
        for (int a = 0; a < AA; a++) lg[a] += m * a2s[a*HIDC + c];
    }
    #pragma unroll
    for (int a = 0; a < AA; a++) out[(b*AA + a)*GG + pos] = lg[a] + b2s[a];
}

// ---------------- launch -----------------------------------------------------
extern "C" void kernel_launch(void* const* d_in, const int* in_sizes, int n_in,
                              void* d_out, int out_size) {
    const float* grid = (const float*)d_in[0];
    // d_in[1], d_in[2]: x_coord / y_coord — unused by the reference.
    const float* h1w = (const float*)d_in[3];
    const float* h1b = (const float*)d_in[4];
    const float* h2w = (const float*)d_in[5];
    const float* h2b = (const float*)d_in[6];
    const float* rw  = (const float*)d_in[7];
    const float* tw  = (const float*)d_in[8];
    const float* a1w = (const float*)d_in[9];
    const float* a1b = (const float*)d_in[10];
    const float* a2w = (const float*)d_in[11];
    const float* a2b = (const float*)d_in[12];
    float* out = (float*)d_out;

    int nprep = HIDC*9*HIDC + HIDC*9*76;
    prep_k<<<(nprep + 255)/256, 256>>>(h2w, rw, tw);
    conv1_k<<<(BB*GG + 255)/256, 256>>>(grid, h1w, h1b);
    conv2_k<<<dim3(G, BB), 224>>>(h2b);
    convrt_k<<<dim3(HP, BB), 128>>>();
    softmax_k<<<(BB*AA*HPHP + 255)/256, 256>>>();
    for (int it = 0; it < KIT; it++)
        vi_step_k<<<(BB*HPHP + 255)/256, 256>>>(it, it == KIT - 1 ? 1 : 0);
    head_k<<<(BB*GG + 255)/256, 256>>>(a1w, a1b, a2w, a2b, out);
}

// round 4
// speedup vs baseline: 3.4699x; 3.4699x over previous
#include <cuda_runtime.h>
#include <cstdint>

// Problem constants
#define BB   128
#define CIN  2
#define HIDC 150
#define AA   8
#define KIT  30
#define G    49
#define HP   51
#define GG   (G*G)      // 2401
#define HPHP (HP*HP)    // 2601
#define CPAD 160        // padded channel-last stride

// ---------------- scratch (device globals; 16B-aligned for vector access) ----
__device__ __align__(16) float g_hT  [BB*GG*CPAD];   // conv1 out, channel-last
__device__ __align__(16) float g_h2T [BB*GG*CPAD];   // conv2 out, channel-last
__device__ __align__(16) float g_tr  [BB*AA*9*HPHP]; // trans -> softmaxed in place
__device__ __align__(16) float g_rew [BB*HPHP];
__device__ __align__(16) float g_vbuf[2][BB*HPHP];
__device__ __align__(16) float g_q   [BB*AA*HPHP];
__device__ __align__(16) float g_wB2 [45*32*160];    // conv2 B tiles  [s][k][n]
__device__ __align__(16) float g_wBrt[45*32*80];     // convrt B tiles [s][k][n]

// ============================ PTX helpers ====================================
__device__ __forceinline__ uint32_t smem_u32(const void* p) {
    uint32_t a;
    asm("{ .reg .u64 t; cvta.to.shared.u64 t, %1; cvt.u32.u64 %0, t; }" : "=r"(a) : "l"(p));
    return a;
}
__device__ __forceinline__ float to_tf32(float x) {
    uint32_t u;
    asm("cvt.rna.tf32.f32 %0, %1;" : "=r"(u) : "f"(x));
    return __uint_as_float(u);
}
__device__ __forceinline__ void cpa16(uint32_t dst, const void* src, uint32_t sz) {
    asm volatile("cp.async.cg.shared.global [%0], [%1], 16, %2;"
                 :: "r"(dst), "l"(src), "r"(sz) : "memory");
}
#define CP_COMMIT() asm volatile("cp.async.commit_group;" ::: "memory")
#define CP_WAIT1()  asm volatile("cp.async.wait_group 1;" ::: "memory")
#define CP_WAIT0()  asm volatile("cp.async.wait_group 0;" ::: "memory")
__device__ __forceinline__ void mma8(float* c, const uint32_t* a, const uint32_t* b) {
    asm volatile("mma.sync.aligned.m16n8k8.row.col.f32.tf32.tf32.f32 "
        "{%0,%1,%2,%3}, {%4,%5,%6,%7}, {%8,%9}, {%0,%1,%2,%3};"
        : "+f"(c[0]), "+f"(c[1]), "+f"(c[2]), "+f"(c[3])
        : "r"(a[0]), "r"(a[1]), "r"(a[2]), "r"(a[3]), "r"(b[0]), "r"(b[1]));
}

// ---------------- weight prep: build tf32 B tiles [s][k][n] ------------------
__global__ void prep_k(const float* __restrict__ h2w,
                       const float* __restrict__ rw,
                       const float* __restrict__ tw) {
    int i = blockIdx.x * blockDim.x + threadIdx.x;
    if (i < 45*32*160) {
        int n = i % 160, k = (i/160) % 32, s = i/(160*32);
        int tap = s/5, ci = (s%5)*32 + k;
        float v = 0.f;
        if (n < HIDC && ci < HIDC) v = h2w[(n*HIDC + ci)*9 + tap];
        g_wB2[i] = to_tf32(v);
    }
    if (i < 45*32*80) {
        int n = i % 80, k = (i/80) % 32, s = i/(80*32);
        int tap = s/5, ci = (s%5)*32 + k;
        float v = 0.f;
        if (ci < HIDC) {
            if (n == 0)      v = rw[ci*9 + tap];
            else if (n < 73) v = tw[((n-1)*HIDC + ci)*9 + tap];
        }
        g_wBrt[i] = to_tf32(v);
    }
}

// -------- conv1 fused with channel-last transpose: grid -> g_hT --------------
__global__ void conv1T_k(const float* __restrict__ gin,
                         const float* __restrict__ w,
                         const float* __restrict__ bias) {
    __shared__ float ws[HIDC*CIN*9];
    __shared__ float bs[HIDC];
    __shared__ __align__(16) float tile[32*164];
    int t = threadIdx.x;
    for (int i = t; i < HIDC*CIN*9; i += 256) ws[i] = w[i];
    for (int i = t; i < HIDC; i += 256) bs[i] = bias[i];
    __syncthreads();
    int pos0 = blockIdx.x * 32, b = blockIdx.y;
    int posi = t & 31, colane = t >> 5;
    int pos = pos0 + posi;
    bool okp = pos < GG;
    int y = okp ? pos / G : 0, x = okp ? pos % G : 0;
    float gv[CIN][9];
    #pragma unroll
    for (int ci = 0; ci < CIN; ci++)
        #pragma unroll
        for (int k = 0; k < 9; k++) {
            int r = y + k/3 - 1, c = x + k%3 - 1;
            gv[ci][k] = (okp && r >= 0 && r < G && c >= 0 && c < G)
                        ? gin[(b*CIN + ci)*GG + r*G + c] : 0.f;
        }
    #pragma unroll
    for (int j = 0; j < 19; j++) {
        int co = colane + 8*j;          // 0..151
        float out = 0.f;
        if (co < HIDC) {
            float acc = bs[co];
            #pragma unroll
            for (int ci = 0; ci < CIN; ci++)
                #pragma unroll
                for (int k = 0; k < 9; k++)
                    acc += gv[ci][k] * ws[(co*CIN + ci)*9 + k];
            out = to_tf32(fmaxf(acc, 0.f));
        }
        tile[posi*164 + co] = out;
    }
    if (t < 32)
        #pragma unroll
        for (int co = 152; co < CPAD; co++) tile[t*164 + co] = 0.f;
    __syncthreads();
    int p2 = t >> 3;
    if (pos0 + p2 < GG) {
        float4* op = (float4*)&g_hT[((size_t)(b*GG + pos0 + p2))*CPAD];
        #pragma unroll
        for (int i = 0; i < 5; i++) {
            int cq = (t & 7) + 8*i;
            op[cq] = *(float4*)&tile[p2*164 + cq*4];
        }
    }
}

// =============== tf32 mma.sync implicit-GEMM conv ============================
// D[pos 128, co NOUT_PAD] = sum over 45 chunks (9 taps x 5 ci-blocks of 32)
// MODE 0: conv2 (g_hT -> relu+bias -> g_h2T channel-last tf32), NFRAG=10 (N=160)
// MODE 1: convrt (g_h2T -> g_rew / g_tr), NFRAG=5 (N=80)
template<int NFRAG, int OW, int PADC, int PTOT, int MODE>
__global__ void __launch_bounds__(256, 2) mma_conv_k(const float* __restrict__ bias) {
    constexpr int NOUT_PAD = NFRAG * 16;
    constexpr int BPAD = NOUT_PAD + 8;
    constexpr int ASZ = 128 * 36;         // floats per A stage
    constexpr int BSZ = 32 * BPAD;        // floats per B stage
    constexpr int BQ  = 32 * NOUT_PAD / 4;
    extern __shared__ __align__(16) float sm[];
    float* biasS = sm + 2*ASZ + 2*BSZ;
    const float* inT = (MODE == 0) ? g_hT : g_h2T;
    const float* wB  = (MODE == 0) ? g_wB2 : g_wBrt;

    int t = threadIdx.x;
    int b = blockIdx.y, tile0 = blockIdx.x * 128;
    uint32_t smb = smem_u32(sm);

    if (MODE == 0) for (int i = t; i < HIDC; i += 256) biasS[i] = bias[i];

    // A-load invariants: thread covers rows m = (t>>3)+32i, 16B quad cq = t&7
    const int cq = t & 7;
    int yy[4], xx[4];
    uint32_t dA[4];
    #pragma unroll
    for (int i = 0; i < 4; i++) {
        int m = (t >> 3) + 32*i;
        int pos = tile0 + m;
        yy[i] = pos / OW;
        xx[i] = pos - yy[i]*OW;
        dA[i] = (uint32_t)(m*36 + cq*4) * 4;
    }
    const float* inB = inT + (size_t)b*GG*CPAD + cq*4;

    auto load_chunk = [&](int s, int stage) {
        int tap = s / 5, cc = s - tap*5;
        int dyp = tap/3 - PADC, dxp = tap%3 - PADC, ci0 = cc*32;
        uint32_t Ab = smb + (uint32_t)stage*ASZ*4;
        #pragma unroll
        for (int i = 0; i < 4; i++) {
            int ir = yy[i] + dyp, ic = xx[i] + dxp;
            bool ok = ((unsigned)ir < G) && ((unsigned)ic < G);
            const float* src = inB + (size_t)(ok ? (ir*G + ic) : 0)*CPAD + ci0;
            cpa16(Ab + dA[i], src, ok ? 16u : 0u);
        }
        uint32_t Bb = smb + (uint32_t)(2*ASZ + stage*BSZ)*4;
        const float* wsrc = wB + (size_t)s*32*NOUT_PAD;
        #pragma unroll
        for (int j = 0; j < (BQ + 255)/256; j++) {
            int q = t + 256*j;
            if (q < BQ) {
                int k = q / (NOUT_PAD/4), n4 = q - k*(NOUT_PAD/4);
                cpa16(Bb + (uint32_t)(k*BPAD + n4*4)*4, wsrc + q*4, 16u);
            }
        }
        CP_COMMIT();
    };

    const int lane = t & 31, wid = t >> 5;
    const int gid = lane >> 2, tig = lane & 3;
    const int m0w = (wid >> 1) * 32, n0w = (wid & 1) * NFRAG * 8;

    float c[2][NFRAG][4];
    #pragma unroll
    for (int mf = 0; mf < 2; mf++)
        #pragma unroll
        for (int nf = 0; nf < NFRAG; nf++)
            #pragma unroll
            for (int e = 0; e < 4; e++) c[mf][nf][e] = 0.f;

    load_chunk(0, 0);
    for (int s = 0; s < 45; s++) {
        int cur = s & 1;
        if (s < 44) { load_chunk(s + 1, cur ^ 1); CP_WAIT1(); }
        else        { CP_WAIT0(); }
        __syncthreads();
        const float* As = sm + cur*ASZ;
        const float* Bs = sm + 2*ASZ + cur*BSZ;
        #pragma unroll
        for (int ks = 0; ks < 4; ks++) {
            int kc = ks*8 + tig;
            uint32_t a[2][4];
            #pragma unroll
            for (int mf = 0; mf < 2; mf++) {
                int r = m0w + mf*16 + gid;
                a[mf][0] = __float_as_uint(As[r*36 + kc]);
                a[mf][1] = __float_as_uint(As[(r+8)*36 + kc]);
                a[mf][2] = __float_as_uint(As[r*36 + kc + 4]);
                a[mf][3] = __float_as_uint(As[(r+8)*36 + kc + 4]);
            }
            #pragma unroll
            for (int nf = 0; nf < NFRAG; nf++) {
                int nc = n0w + nf*8 + gid;
                uint32_t bv[2];
                bv[0] = __float_as_uint(Bs[kc*BPAD + nc]);
                bv[1] = __float_as_uint(Bs[(kc+4)*BPAD + nc]);
                mma8(c[0][nf], a[0], bv);
                mma8(c[1][nf], a[1], bv);
            }
        }
        __syncthreads();
    }

    // ---- epilogue ----
    #pragma unroll
    for (int mf = 0; mf < 2; mf++) {
        #pragma unroll
        for (int rr = 0; rr < 2; rr++) {
            int pos = tile0 + m0w + mf*16 + gid + rr*8;
            if (pos >= PTOT) continue;
            if (MODE == 0) {
                float* op = &g_h2T[((size_t)(b*GG + pos))*CPAD];
                #pragma unroll
                for (int nf = 0; nf < NFRAG; nf++) {
                    int co = n0w + nf*8 + 2*tig;
                    float v0 = c[mf][nf][rr*2 + 0], v1 = c[mf][nf][rr*2 + 1];
                    float2 o;
                    o.x = (co   < HIDC) ? to_tf32(fmaxf(v0 + biasS[co],   0.f)) : 0.f;
                    o.y = (co+1 < HIDC) ? to_tf32(fmaxf(v1 + biasS[co+1], 0.f)) : 0.f;
                    *(float2*)&op[co] = o;
                }
            } else {
                #pragma unroll
                for (int nf = 0; nf < NFRAG; nf++) {
                    int co = n0w + nf*8 + 2*tig;
                    float v0 = c[mf][nf][rr*2 + 0], v1 = c[mf][nf][rr*2 + 1];
                    if (co == 0)      g_rew[b*HPHP + pos] = v0;
                    else if (co < 73) g_tr[((size_t)(b*72 + co - 1))*HPHP + pos] = v0;
                    if (co + 1 < 73)  g_tr[((size_t)(b*72 + co))*HPHP + pos] = v1;
                }
            }
        }
    }
}

// ---------------- softmax over 9 taps ---------------------------------------
__global__ void softmax_k() {
    int tid = blockIdx.x * blockDim.x + threadIdx.x;
    if (tid >= BB*AA*HPHP) return;
    int pos = tid % HPHP;
    int ba  = tid / HPHP;
    size_t base = (size_t)ba*9*HPHP + pos;
    float v[9];
    float m = -1e30f;
    #pragma unroll
    for (int k = 0; k < 9; k++) { v[k] = g_tr[base + (size_t)k*HPHP]; m = fmaxf(m, v[k]); }
    float s = 0.f;
    #pragma unroll
    for (int k = 0; k < 9; k++) { v[k] = expf(v[k] - m); s += v[k]; }
    float inv = 1.f / s;
    #pragma unroll
    for (int k = 0; k < 9; k++) g_tr[base + (size_t)k*HPHP] = v[k] * inv;
}

// ---------------- one value-iteration step ----------------------------------
__global__ void vi_step_k(int iter, int store_q) {
    int tid = blockIdx.x * blockDim.x + threadIdx.x;
    if (tid >= BB*HPHP) return;
    int b = tid / HPHP, pos = tid % HPHP, y = pos / HP, x = pos % HP;
    const float* vin = g_vbuf[(iter & 1) ^ 1];
    float p[9];
    if (iter == 0) {
        #pragma unroll
        for (int k = 0; k < 9; k++) p[k] = 0.f;
    } else {
        #pragma unroll
        for (int k = 0; k < 9; k++) {
            int r = y + k/3 - 1, c = x + k%3 - 1;
            p[k] = (r >= 0 && r < HP && c >= 0 && c < HP)
                   ? vin[b*HPHP + r*HP + c] : 0.f;
        }
    }
    float r0 = g_rew[tid];
    float vmax = -1e30f;
    #pragma unroll
    for (int a = 0; a < AA; a++) {
        size_t base = ((size_t)(b*72 + a*9))*HPHP + pos;
        float q = r0;
        #pragma unroll
        for (int k = 0; k < 9; k++) q += g_tr[base + (size_t)k*HPHP] * p[k];
        if (store_q) g_q[(b*AA + a)*HPHP + pos] = q;
        vmax = fmaxf(vmax, q);
    }
    g_vbuf[iter & 1][tid] = vmax;
}

// ---------------- head -------------------------------------------------------
__global__ void head_k(const float* __restrict__ a1w, const float* __restrict__ a1b,
                       const float* __restrict__ a2w, const float* __restrict__ a2b,
                       float* __restrict__ out) {
    __shared__ float a1s[HIDC*AA];
    __shared__ float a2s[AA*HIDC];
    __shared__ float b1s[HIDC];
    __shared__ float b2s[AA];
    int t = threadIdx.x;
    for (int i = t; i < HIDC*AA; i += blockDim.x) { a1s[i] = a1w[i]; a2s[i] = a2w[i]; }
    for (int i = t; i < HIDC; i += blockDim.x) b1s[i] = a1b[i];
    if (t < AA) b2s[t] = a2b[t];
    __syncthreads();
    int tid = blockIdx.x * blockDim.x + t;
    if (tid >= BB*GG) return;
    int b = tid / GG, pos = tid % GG, y = pos / G, x = pos % G;
    float qv[AA];
    #pragma unroll
    for (int a = 0; a < AA; a++) qv[a] = g_q[(b*AA + a)*HPHP + y*HP + x];
    float lg[AA];
    #pragma unroll
    for (int a = 0; a < AA; a++) lg[a] = 0.f;
    for (int c = 0; c < HIDC; c++) {
        float m = b1s[c];
        #pragma unroll
        for (int a = 0; a < AA; a++) m += qv[a] * a1s[c*AA + a];
        m = fmaxf(m, 0.f);
        #pragma unroll
        for (int a = 0; a < AA; a++) lg[a] += m * a2s[a*HIDC + c];
    }
    #pragma unroll
    for (int a = 0; a < AA; a++) out[(b*AA + a)*GG + pos] = lg[a] + b2s[a];
}

// ---------------- launch -----------------------------------------------------
extern "C" void kernel_launch(void* const* d_in, const int* in_sizes, int n_in,
                              void* d_out, int out_size) {
    const float* grid = (const float*)d_in[0];
    const float* h1w = (const float*)d_in[3];
    const float* h1b = (const float*)d_in[4];
    const float* h2w = (const float*)d_in[5];
    const float* h2b = (const float*)d_in[6];
    const float* rw  = (const float*)d_in[7];
    const float* tw  = (const float*)d_in[8];
    const float* a1w = (const float*)d_in[9];
    const float* a1b = (const float*)d_in[10];
    const float* a2w = (const float*)d_in[11];
    const float* a2b = (const float*)d_in[12];
    float* out = (float*)d_out;

    // dynamic smem: 2*A(128x36) + 2*B(32x(N+8)) + bias
    const int SMEM2  = (2*128*36 + 2*32*168 + 160) * 4;   // 80512 B
    const int SMEMRT = (2*128*36 + 2*32*88) * 4;          // 59392 B
    cudaFuncSetAttribute(mma_conv_k<10, G, 1, GG, 0>,
                         cudaFuncAttributeMaxDynamicSharedMemorySize, SMEM2);
    cudaFuncSetAttribute(mma_conv_k<5, HP, 2, HPHP, 1>,
                         cudaFuncAttributeMaxDynamicSharedMemorySize, SMEMRT);

    prep_k<<<(45*32*160 + 255)/256, 256>>>(h2w, rw, tw);
    conv1T_k<<<dim3((GG + 31)/32, BB), 256>>>(grid, h1w, h1b);
    mma_conv_k<10, G, 1, GG, 0><<<dim3((GG + 127)/128, BB), 256, SMEM2>>>(h2b);
    mma_conv_k<5, HP, 2, HPHP, 1><<<dim3((HPHP + 127)/128, BB), 256, SMEMRT>>>(nullptr);
    softmax_k<<<(BB*AA*HPHP + 255)/256, 256>>>();
    for (int it = 0; it < KIT; it++)
        vi_step_k<<<(BB*HPHP + 255)/256, 256>>>(it, it == KIT - 1 ? 1 : 0);
    head_k<<<(BB*GG + 255)/256, 256>>>(a1w, a1b, a2w, a2b, out);
}